// round 15
// baseline (speedup 1.0000x reference)
#include <cuda_runtime.h>
#include <cuda_fp16.h>
#include <cstdint>

#define NN 100000
#define NE 1600000
#define NF 128
#define NH 64
#define NC 16
#define NBLK 391           // ceil(NN/256)
#define NBLKM 782          // ceil(NN/128) mma gemm1 tiles
// gemm1 tile chunk boundaries across the 5 fat kernels
#define TA 250
#define TB 60
#define TC 60
#define TD 60
#define TE (NBLKM - TA - TB - TC - TD)   // 352
#define EDGE_BLKS 1024
#define SAS 72             // smem stride (halves) for A/B tiles

// Scratch (__device__ globals only), 256B-aligned
__device__ __align__(256) __half g_h1[(size_t)NN * NH];    // fp16(x @ W1)
__device__ __align__(256) __half g_agg1[(size_t)NN * NH];  // fp16 layer-1 aggregate
__device__ __align__(256) __half g_h2[(size_t)NN * NC];    // fp16 (agg1 @ W2) * dinv
__device__ __align__(256) float g_dinv[NN];
__device__ __align__(256) int   g_cnt[NN];
__device__ __align__(256) int   g_rowptr[NN];
__device__ __align__(256) int   g_fill[NN];
__device__ __align__(256) int   g_srcv[NE];
__device__ __align__(256) int   g_bsum[NBLK];
__device__ __align__(256) int   g_boff[NBLK];

// ---------------------------------------------------------------------------
__global__ void zero_kernel() {
    int i = blockIdx.x * blockDim.x + threadIdx.x;
    if (i < NN) { g_cnt[i] = 0; g_fill[i] = 0; }
}

// ---------------------------------------------------------------------------
// MMA helpers
// ---------------------------------------------------------------------------
__device__ __forceinline__ uint32_t smem_u32(const void* p) {
    return (uint32_t)__cvta_generic_to_shared(p);
}
__device__ __forceinline__ void ldsm_x4(uint32_t* r, uint32_t addr) {
    asm volatile("ldmatrix.sync.aligned.m8n8.x4.shared.b16 {%0,%1,%2,%3}, [%4];"
                 : "=r"(r[0]), "=r"(r[1]), "=r"(r[2]), "=r"(r[3]) : "r"(addr));
}
__device__ __forceinline__ void ldsm_x4_t(uint32_t* r, uint32_t addr) {
    asm volatile("ldmatrix.sync.aligned.m8n8.x4.trans.shared.b16 {%0,%1,%2,%3}, [%4];"
                 : "=r"(r[0]), "=r"(r[1]), "=r"(r[2]), "=r"(r[3]) : "r"(addr));
}
__device__ __forceinline__ void mma_16816(float* d, const uint32_t* a, const uint32_t* b) {
    asm volatile("mma.sync.aligned.m16n8k16.row.col.f32.f16.f16.f32 "
                 "{%0,%1,%2,%3}, {%4,%5,%6,%7}, {%8,%9}, {%0,%1,%2,%3};"
                 : "+f"(d[0]), "+f"(d[1]), "+f"(d[2]), "+f"(d[3])
                 : "r"(a[0]), "r"(a[1]), "r"(a[2]), "r"(a[3]), "r"(b[0]), "r"(b[1]));
}

// ---------------------------------------------------------------------------
// GEMM1 tile via tensor cores: 128 rows x 64 cols, K=128, 8 warps.
// ---------------------------------------------------------------------------
__device__ __forceinline__ void gemm1_tile_mma(int b, const float* __restrict__ x,
                                               const float* __restrict__ W1,
                                               __half* sA, __half* sB) {
    int tid = threadIdx.x;
    int wid = tid >> 5, lane = tid & 31;
    int r0 = b * 128;
    int m0 = (wid >> 1) * 32;
    int n0 = (wid & 1) * 32;

    for (int i = tid; i < NF * NH; i += 256) {
        int k = i >> 6, n = i & 63;
        sB[k * SAS + n] = __float2half_rn(W1[i]);
    }

    float acc[2][4][4];
#pragma unroll
    for (int mi = 0; mi < 2; mi++)
#pragma unroll
        for (int ni = 0; ni < 4; ni++)
#pragma unroll
            for (int q = 0; q < 4; q++) acc[mi][ni][q] = 0.0f;

    for (int kc = 0; kc < NF; kc += 64) {
        __syncthreads();
        for (int i = tid; i < 128 * 64; i += 256) {
            int m = i >> 6, kk = i & 63;
            int gr = r0 + m;
            float v = (gr < NN) ? x[(size_t)gr * NF + kc + kk] : 0.0f;
            sA[m * SAS + kk] = __float2half_rn(v);
        }
        __syncthreads();
#pragma unroll
        for (int ks = 0; ks < 4; ks++) {
            uint32_t afr[2][4];
#pragma unroll
            for (int mi = 0; mi < 2; mi++) {
                const __half* p = &sA[(m0 + mi * 16 + (lane & 15)) * SAS
                                      + ks * 16 + (lane >> 4) * 8];
                ldsm_x4(afr[mi], smem_u32(p));
            }
            uint32_t bfr[4][2];
#pragma unroll
            for (int nj = 0; nj < 2; nj++) {
                uint32_t t[4];
                const __half* p = &sB[(kc + ks * 16 + (lane & 15)) * SAS
                                      + n0 + nj * 16 + (lane >> 4) * 8];
                ldsm_x4_t(t, smem_u32(p));
                bfr[nj * 2 + 0][0] = t[0]; bfr[nj * 2 + 0][1] = t[1];
                bfr[nj * 2 + 1][0] = t[2]; bfr[nj * 2 + 1][1] = t[3];
            }
#pragma unroll
            for (int mi = 0; mi < 2; mi++)
#pragma unroll
                for (int ni = 0; ni < 4; ni++)
                    mma_16816(acc[mi][ni], afr[mi], bfr[ni]);
        }
    }

#pragma unroll
    for (int mi = 0; mi < 2; mi++) {
        int rb = r0 + m0 + mi * 16 + (lane >> 2);
#pragma unroll
        for (int ni = 0; ni < 4; ni++) {
            int c = n0 + ni * 8 + 2 * (lane & 3);
            if (rb < NN)
                *(__half2*)&g_h1[(size_t)rb * NH + c] =
                    __floats2half2_rn(acc[mi][ni][0], acc[mi][ni][1]);
            if (rb + 8 < NN)
                *(__half2*)&g_h1[(size_t)(rb + 8) * NH + c] =
                    __floats2half2_rn(acc[mi][ni][2], acc[mi][ni][3]);
        }
    }
}

// ---- scan bodies ----------------------------------------------------------
__device__ __forceinline__ void scan1_body(int sb) {
    __shared__ int s[256];
    int tid = threadIdx.x;
    int gid = sb * 256 + tid;
    int v = (gid < NN) ? g_cnt[gid] : 0;
    s[tid] = v;
    __syncthreads();
#pragma unroll
    for (int off = 1; off < 256; off <<= 1) {
        int t = (tid >= off) ? s[tid - off] : 0;
        __syncthreads();
        s[tid] += t;
        __syncthreads();
    }
    if (gid < NN) g_rowptr[gid] = s[tid] - v;
    if (tid == 255) g_bsum[sb] = s[255];
}

__device__ __forceinline__ void scan2_body() {
    __shared__ int s2[256];
    int tid = threadIdx.x;
    int i0 = 2 * tid, i1 = 2 * tid + 1;
    int v0 = (i0 < NBLK) ? g_bsum[i0] : 0;
    int v1 = (i1 < NBLK) ? g_bsum[i1] : 0;
    int sum = v0 + v1;
    s2[tid] = sum;
    __syncthreads();
#pragma unroll
    for (int off = 1; off < 256; off <<= 1) {
        int t = (tid >= off) ? s2[tid - off] : 0;
        __syncthreads();
        s2[tid] += t;
        __syncthreads();
    }
    int excl = s2[tid] - sum;
    if (i0 < NBLK) g_boff[i0] = excl;
    if (i1 < NBLK) g_boff[i1] = excl + v0;
}

__device__ __forceinline__ void scan3_body(int sb) {
    int gid = sb * 256 + threadIdx.x;
    if (gid < NN) {
        g_rowptr[gid] += g_boff[sb];
        int d = g_cnt[gid];
        g_dinv[gid] = (d > 0) ? rsqrtf((float)d) : 0.0f;
    }
}

// ---- fat kernels: serial-stage blocks FIRST, then gemm tiles --------------
__global__ __launch_bounds__(256) void fatA_kernel(const float* __restrict__ x,
                                                   const float* __restrict__ W1,
                                                   const int* __restrict__ ei) {
    __shared__ __half sA[128 * SAS];
    __shared__ __half sB[128 * SAS];
    int b = blockIdx.x;
    if (b < EDGE_BLKS) {
        int stride = EDGE_BLKS * 256;
        for (int e = b * 256 + threadIdx.x; e < NE; e += stride)
            atomicAdd(&g_cnt[ei[NE + e]], 1);
    } else {
        gemm1_tile_mma(b - EDGE_BLKS, x, W1, sA, sB);          // tiles [0,TA)
    }
}

__global__ __launch_bounds__(256) void fatB_kernel(const float* __restrict__ x,
                                                   const float* __restrict__ W1) {
    __shared__ __half sA[128 * SAS];
    __shared__ __half sB[128 * SAS];
    int b = blockIdx.x;
    if (b < NBLK) scan1_body(b);
    else gemm1_tile_mma(b - NBLK + TA, x, W1, sA, sB);          // tiles [TA,TA+TB)
}

__global__ __launch_bounds__(256) void fatC_kernel(const float* __restrict__ x,
                                                   const float* __restrict__ W1) {
    __shared__ __half sA[128 * SAS];
    __shared__ __half sB[128 * SAS];
    int b = blockIdx.x;
    if (b == 0) scan2_body();
    else gemm1_tile_mma(b - 1 + TA + TB, x, W1, sA, sB);        // tiles [TA+TB,+TC)
}

__global__ __launch_bounds__(256) void fatD_kernel(const float* __restrict__ x,
                                                   const float* __restrict__ W1) {
    __shared__ __half sA[128 * SAS];
    __shared__ __half sB[128 * SAS];
    int b = blockIdx.x;
    if (b < NBLK) scan3_body(b);
    else gemm1_tile_mma(b - NBLK + TA + TB + TC, x, W1, sA, sB); // tiles [..,+TD)
}

__global__ __launch_bounds__(256) void fatE_kernel(const float* __restrict__ x,
                                                   const float* __restrict__ W1,
                                                   const int* __restrict__ ei) {
    __shared__ __half sA[128 * SAS];
    __shared__ __half sB[128 * SAS];
    int b = blockIdx.x;
    if (b < EDGE_BLKS) {
        int stride = EDGE_BLKS * 256;
        for (int e = b * 256 + threadIdx.x; e < NE; e += stride) {
            int row = ei[e];
            int col = ei[NE + e];
            int pos = atomicAdd(&g_fill[col], 1);
            g_srcv[g_rowptr[col] + pos] = row;
        }
    } else {
        gemm1_tile_mma(b - EDGE_BLKS + TA + TB + TC + TD, x, W1, sA, sB); // [..,782)
    }
}

// ---------------------------------------------------------------------------
// Gather 1 (warp per node): agg1[n] = fp16( dinv[n] * sum_s dinv[s] * h1[s] )
// ---------------------------------------------------------------------------
__global__ __launch_bounds__(256) void gather1_kernel() {
    int w = (blockIdx.x * blockDim.x + threadIdx.x) >> 5;
    int lane = threadIdx.x & 31;
    if (w >= NN) return;

    int start = g_rowptr[w];
    int deg = g_cnt[w];
    float ax = 0.0f, ay = 0.0f;
    const unsigned int* h1u = (const unsigned int*)g_h1;
    int i = 0;
    for (; i + 4 <= deg; i += 4) {
        int s0 = g_srcv[start + i + 0];
        int s1 = g_srcv[start + i + 1];
        int s2 = g_srcv[start + i + 2];
        int s3 = g_srcv[start + i + 3];
        float d0 = g_dinv[s0], d1 = g_dinv[s1], d2 = g_dinv[s2], d3 = g_dinv[s3];
        float2 v0 = __half22float2(*(const __half2*)&h1u[s0 * 32 + lane]);
        float2 v1 = __half22float2(*(const __half2*)&h1u[s1 * 32 + lane]);
        float2 v2 = __half22float2(*(const __half2*)&h1u[s2 * 32 + lane]);
        float2 v3 = __half22float2(*(const __half2*)&h1u[s3 * 32 + lane]);
        ax += v0.x * d0 + v1.x * d1 + v2.x * d2 + v3.x * d3;
        ay += v0.y * d0 + v1.y * d1 + v2.y * d2 + v3.y * d3;
    }
    for (; i < deg; i++) {
        int s0 = g_srcv[start + i];
        float d0 = g_dinv[s0];
        float2 v0 = __half22float2(*(const __half2*)&h1u[s0 * 32 + lane]);
        ax += v0.x * d0; ay += v0.y * d0;
    }
    float dc = g_dinv[w];
    ((__half2*)&g_agg1[(size_t)w * NH])[lane] = __floats2half2_rn(ax * dc, ay * dc);
}

// ---------------------------------------------------------------------------
// GEMM2: h2[N,16] = fp16( (agg1[N,64] @ W2[64,16]) * dinv[row] ), fp16 agg1 in
// ---------------------------------------------------------------------------
__global__ __launch_bounds__(256) void gemm2_kernel(const float* __restrict__ W2) {
    __shared__ float sW[NH * NC];
    int tid = threadIdx.x;
    for (int i = tid; i < NH * NC; i += 256) sW[i] = W2[i];
    __syncthreads();

    int r = blockIdx.x * 256 + tid;
    if (r >= NN) return;

    float acc[16];
#pragma unroll
    for (int c = 0; c < 16; c++) acc[c] = 0.0f;

    const __half2* xp = (const __half2*)&g_agg1[(size_t)r * NH];
#pragma unroll
    for (int k2 = 0; k2 < 32; k2++) {
        float2 xv = __half22float2(xp[k2]);
        const float* wp0 = &sW[(k2 * 2 + 0) * NC];
        const float* wp1 = &sW[(k2 * 2 + 1) * NC];
#pragma unroll
        for (int c = 0; c < 16; c++) acc[c] += xv.x * wp0[c] + xv.y * wp1[c];
    }

    float dv = g_dinv[r];
    __half2* op = (__half2*)&g_h2[(size_t)r * NC];
#pragma unroll
    for (int q = 0; q < 8; q++)
        op[q] = __floats2half2_rn(acc[2 * q] * dv, acc[2 * q + 1] * dv);
}

// ---------------------------------------------------------------------------
// Gather 2 + log_softmax fused: 2 nodes per warp (16 lanes each), fp16 h2
// ---------------------------------------------------------------------------
__global__ __launch_bounds__(256) void gather2_softmax_kernel(float* __restrict__ out) {
    int w = (blockIdx.x * blockDim.x + threadIdx.x) >> 5;
    int lane = threadIdx.x & 31;
    int node = w * 2 + (lane >> 4);
    int l = lane & 15;
    if (node >= NN) return;

    int start = g_rowptr[node];
    int deg = g_cnt[node];
    float acc = 0.0f;
    int i = 0;
    for (; i + 4 <= deg; i += 4) {
        int s0 = g_srcv[start + i + 0];
        int s1 = g_srcv[start + i + 1];
        int s2 = g_srcv[start + i + 2];
        int s3 = g_srcv[start + i + 3];
        acc += __half2float(g_h2[(size_t)s0 * NC + l]) + __half2float(g_h2[(size_t)s1 * NC + l])
             + __half2float(g_h2[(size_t)s2 * NC + l]) + __half2float(g_h2[(size_t)s3 * NC + l]);
    }
    for (; i < deg; i++) acc += __half2float(g_h2[(size_t)g_srcv[start + i] * NC + l]);
    acc *= g_dinv[node];

    float m = acc;
#pragma unroll
    for (int off = 8; off > 0; off >>= 1)
        m = fmaxf(m, __shfl_xor_sync(0xffffffffu, m, off, 16));
    float ex = expf(acc - m);
    float s = ex;
#pragma unroll
    for (int off = 8; off > 0; off >>= 1)
        s += __shfl_xor_sync(0xffffffffu, s, off, 16);
    out[(size_t)node * NC + l] = (acc - m) - logf(s);
}

// ---------------------------------------------------------------------------
extern "C" void kernel_launch(void* const* d_in, const int* in_sizes, int n_in,
                              void* d_out, int out_size) {
    const float* x = (const float*)d_in[0];
    const int* ei = (const int*)d_in[1];
    const float* W1 = (const float*)d_in[2];
    const float* W2 = (const float*)d_in[3];
    float* out = (float*)d_out;

    zero_kernel<<<NBLK, 256>>>();
    fatA_kernel<<<EDGE_BLKS + TA, 256>>>(x, W1, ei);   // deg ∥ gemm tiles
    fatB_kernel<<<NBLK + TB, 256>>>(x, W1);            // scan1 ∥ gemm tiles
    fatC_kernel<<<1 + TC, 256>>>(x, W1);               // scan2 ∥ gemm tiles
    fatD_kernel<<<NBLK + TD, 256>>>(x, W1);            // scan3 ∥ gemm tiles
    fatE_kernel<<<EDGE_BLKS + TE, 256>>>(x, W1, ei);   // fill ∥ gemm tiles
    gather1_kernel<<<(NN * 32 + 255) / 256, 256>>>();
    gemm2_kernel<<<NBLK, 256>>>(W2);
    gather2_softmax_kernel<<<((NN + 1) / 2 * 32 + 255) / 256, 256>>>(out);
}

// round 17
// speedup vs baseline: 1.7207x; 1.7207x over previous
#include <cuda_runtime.h>
#include <cuda_fp16.h>
#include <cstdint>

#define NN 100000
#define NE 1600000
#define NF 128
#define NH 64
#define NC 16
#define NBLK 391           // ceil(NN/256)
#define NBLKM 782          // ceil(NN/128) mma gemm1 tiles
#define G1A 391            // gemm1 tiles in fat kernel A
#define G1B (NBLKM - G1A)  // gemm1 tiles in fat kernel B
#define EDGE_BLKS 1024
#define SAS 72             // smem stride (halves) for A/B tiles

// Scratch (__device__ globals only), 256B-aligned
__device__ __align__(256) __half g_h1[(size_t)NN * NH];    // fp16(x @ W1)
__device__ __align__(256) __half g_agg1[(size_t)NN * NH];  // fp16 layer-1 aggregate
__device__ __align__(256) __half g_h2[(size_t)NN * NC];    // fp16 (agg1 @ W2) * dinv
__device__ __align__(256) float g_dinv[NN];
__device__ __align__(256) int   g_cnt[NN];
__device__ __align__(256) int   g_rowptr[NN];
__device__ __align__(256) int   g_fill[NN];
__device__ __align__(256) int   g_srcv[NE];
__device__ int g_cursor;

// ---------------------------------------------------------------------------
__global__ void zero_kernel() {
    int i = blockIdx.x * blockDim.x + threadIdx.x;
    if (i < NN) { g_cnt[i] = 0; g_fill[i] = 0; }
    if (i == 0) g_cursor = 0;
}

// ---------------------------------------------------------------------------
// MMA helpers
// ---------------------------------------------------------------------------
__device__ __forceinline__ uint32_t smem_u32(const void* p) {
    return (uint32_t)__cvta_generic_to_shared(p);
}
__device__ __forceinline__ void ldsm_x4(uint32_t* r, uint32_t addr) {
    asm volatile("ldmatrix.sync.aligned.m8n8.x4.shared.b16 {%0,%1,%2,%3}, [%4];"
                 : "=r"(r[0]), "=r"(r[1]), "=r"(r[2]), "=r"(r[3]) : "r"(addr));
}
__device__ __forceinline__ void ldsm_x4_t(uint32_t* r, uint32_t addr) {
    asm volatile("ldmatrix.sync.aligned.m8n8.x4.trans.shared.b16 {%0,%1,%2,%3}, [%4];"
                 : "=r"(r[0]), "=r"(r[1]), "=r"(r[2]), "=r"(r[3]) : "r"(addr));
}
__device__ __forceinline__ void mma_16816(float* d, const uint32_t* a, const uint32_t* b) {
    asm volatile("mma.sync.aligned.m16n8k16.row.col.f32.f16.f16.f32 "
                 "{%0,%1,%2,%3}, {%4,%5,%6,%7}, {%8,%9}, {%0,%1,%2,%3};"
                 : "+f"(d[0]), "+f"(d[1]), "+f"(d[2]), "+f"(d[3])
                 : "r"(a[0]), "r"(a[1]), "r"(a[2]), "r"(a[3]), "r"(b[0]), "r"(b[1]));
}

// ---------------------------------------------------------------------------
// GEMM1 tile via tensor cores: 128 rows x 64 cols, K=128, 8 warps.
// ---------------------------------------------------------------------------
__device__ __forceinline__ void gemm1_tile_mma(int b, const float* __restrict__ x,
                                               const float* __restrict__ W1,
                                               __half* sA, __half* sB) {
    int tid = threadIdx.x;
    int wid = tid >> 5, lane = tid & 31;
    int r0 = b * 128;
    int m0 = (wid >> 1) * 32;
    int n0 = (wid & 1) * 32;

    for (int i = tid; i < NF * NH; i += 256) {
        int k = i >> 6, n = i & 63;
        sB[k * SAS + n] = __float2half_rn(W1[i]);
    }

    float acc[2][4][4];
#pragma unroll
    for (int mi = 0; mi < 2; mi++)
#pragma unroll
        for (int ni = 0; ni < 4; ni++)
#pragma unroll
            for (int q = 0; q < 4; q++) acc[mi][ni][q] = 0.0f;

    for (int kc = 0; kc < NF; kc += 64) {
        __syncthreads();
        for (int i = tid; i < 128 * 64; i += 256) {
            int m = i >> 6, kk = i & 63;
            int gr = r0 + m;
            float v = (gr < NN) ? x[(size_t)gr * NF + kc + kk] : 0.0f;
            sA[m * SAS + kk] = __float2half_rn(v);
        }
        __syncthreads();
#pragma unroll
        for (int ks = 0; ks < 4; ks++) {
            uint32_t afr[2][4];
#pragma unroll
            for (int mi = 0; mi < 2; mi++) {
                const __half* p = &sA[(m0 + mi * 16 + (lane & 15)) * SAS
                                      + ks * 16 + (lane >> 4) * 8];
                ldsm_x4(afr[mi], smem_u32(p));
            }
            uint32_t bfr[4][2];
#pragma unroll
            for (int nj = 0; nj < 2; nj++) {
                uint32_t t[4];
                const __half* p = &sB[(kc + ks * 16 + (lane & 15)) * SAS
                                      + n0 + nj * 16 + (lane >> 4) * 8];
                ldsm_x4_t(t, smem_u32(p));
                bfr[nj * 2 + 0][0] = t[0]; bfr[nj * 2 + 0][1] = t[1];
                bfr[nj * 2 + 1][0] = t[2]; bfr[nj * 2 + 1][1] = t[3];
            }
#pragma unroll
            for (int mi = 0; mi < 2; mi++)
#pragma unroll
                for (int ni = 0; ni < 4; ni++)
                    mma_16816(acc[mi][ni], afr[mi], bfr[ni]);
        }
    }

#pragma unroll
    for (int mi = 0; mi < 2; mi++) {
        int rb = r0 + m0 + mi * 16 + (lane >> 2);
#pragma unroll
        for (int ni = 0; ni < 4; ni++) {
            int c = n0 + ni * 8 + 2 * (lane & 3);
            if (rb < NN)
                *(__half2*)&g_h1[(size_t)rb * NH + c] =
                    __floats2half2_rn(acc[mi][ni][0], acc[mi][ni][1]);
            if (rb + 8 < NN)
                *(__half2*)&g_h1[(size_t)(rb + 8) * NH + c] =
                    __floats2half2_rn(acc[mi][ni][2], acc[mi][ni][3]);
        }
    }
}

// Fat kernel A: gemm1 tiles [0, G1A) ∥ degree histogram
__global__ __launch_bounds__(256) void fatA_kernel(const float* __restrict__ x,
                                                   const float* __restrict__ W1,
                                                   const int* __restrict__ ei) {
    __shared__ __half sA[128 * SAS];
    __shared__ __half sB[128 * SAS];
    int b = blockIdx.x;
    if (b < G1A) {
        gemm1_tile_mma(b, x, W1, sA, sB);
    } else {
        int stride = (gridDim.x - G1A) * 256;
        for (int e = (b - G1A) * 256 + threadIdx.x; e < NE; e += stride)
            atomicAdd(&g_cnt[ei[NE + e]], 1);
    }
}

// Fat kernel B: gemm1 tiles [G1A, NBLKM) ∥ CSR fill
__global__ __launch_bounds__(256) void fatB_kernel(const float* __restrict__ x,
                                                   const float* __restrict__ W1,
                                                   const int* __restrict__ ei) {
    __shared__ __half sA[128 * SAS];
    __shared__ __half sB[128 * SAS];
    int b = blockIdx.x;
    if (b < G1B) {
        gemm1_tile_mma(b + G1A, x, W1, sA, sB);
    } else {
        int stride = (gridDim.x - G1B) * 256;
        for (int e = (b - G1B) * 256 + threadIdx.x; e < NE; e += stride) {
            int row = ei[e];
            int col = ei[NE + e];
            int pos = atomicAdd(&g_fill[col], 1);
            g_srcv[g_rowptr[col] + pos] = row;
        }
    }
}

// ---------------------------------------------------------------------------
// Single-kernel "scan": CSR ranges need not be in node order — each block
// grabs a contiguous region for its 256 nodes via one atomicAdd on a global
// cursor, then lays out its nodes inside it. Also computes dinv.
// ---------------------------------------------------------------------------
__global__ __launch_bounds__(256) void scan_fused_kernel() {
    __shared__ int s[256];
    __shared__ int base;
    int tid = threadIdx.x;
    int gid = blockIdx.x * 256 + tid;
    int v = (gid < NN) ? g_cnt[gid] : 0;
    s[tid] = v;
    __syncthreads();
#pragma unroll
    for (int off = 1; off < 256; off <<= 1) {
        int t = (tid >= off) ? s[tid - off] : 0;
        __syncthreads();
        s[tid] += t;
        __syncthreads();
    }
    if (tid == 255) base = atomicAdd(&g_cursor, s[255]);
    __syncthreads();
    if (gid < NN) {
        g_rowptr[gid] = base + s[tid] - v;
        g_dinv[gid] = (v > 0) ? rsqrtf((float)v) : 0.0f;
    }
}

// ---------------------------------------------------------------------------
// Gather 1 (warp per node): agg1[n] = fp16( dinv[n] * sum_s dinv[s] * h1[s] )
// ---------------------------------------------------------------------------
__global__ __launch_bounds__(256) void gather1_kernel() {
    int w = (blockIdx.x * blockDim.x + threadIdx.x) >> 5;
    int lane = threadIdx.x & 31;
    if (w >= NN) return;

    int start = g_rowptr[w];
    int deg = g_cnt[w];
    float ax = 0.0f, ay = 0.0f;
    const unsigned int* h1u = (const unsigned int*)g_h1;
    int i = 0;
    for (; i + 4 <= deg; i += 4) {
        int s0 = g_srcv[start + i + 0];
        int s1 = g_srcv[start + i + 1];
        int s2 = g_srcv[start + i + 2];
        int s3 = g_srcv[start + i + 3];
        float d0 = g_dinv[s0], d1 = g_dinv[s1], d2 = g_dinv[s2], d3 = g_dinv[s3];
        float2 v0 = __half22float2(*(const __half2*)&h1u[s0 * 32 + lane]);
        float2 v1 = __half22float2(*(const __half2*)&h1u[s1 * 32 + lane]);
        float2 v2 = __half22float2(*(const __half2*)&h1u[s2 * 32 + lane]);
        float2 v3 = __half22float2(*(const __half2*)&h1u[s3 * 32 + lane]);
        ax += v0.x * d0 + v1.x * d1 + v2.x * d2 + v3.x * d3;
        ay += v0.y * d0 + v1.y * d1 + v2.y * d2 + v3.y * d3;
    }
    for (; i < deg; i++) {
        int s0 = g_srcv[start + i];
        float d0 = g_dinv[s0];
        float2 v0 = __half22float2(*(const __half2*)&h1u[s0 * 32 + lane]);
        ax += v0.x * d0; ay += v0.y * d0;
    }
    float dc = g_dinv[w];
    ((__half2*)&g_agg1[(size_t)w * NH])[lane] = __floats2half2_rn(ax * dc, ay * dc);
}

// ---------------------------------------------------------------------------
// GEMM2: h2[N,16] = fp16( (agg1[N,64] @ W2[64,16]) * dinv[row] ), fp16 agg1 in
// ---------------------------------------------------------------------------
__global__ __launch_bounds__(256) void gemm2_kernel(const float* __restrict__ W2) {
    __shared__ float sW[NH * NC];
    int tid = threadIdx.x;
    for (int i = tid; i < NH * NC; i += 256) sW[i] = W2[i];
    __syncthreads();

    int r = blockIdx.x * 256 + tid;
    if (r >= NN) return;

    float acc[16];
#pragma unroll
    for (int c = 0; c < 16; c++) acc[c] = 0.0f;

    const __half2* xp = (const __half2*)&g_agg1[(size_t)r * NH];
#pragma unroll
    for (int k2 = 0; k2 < 32; k2++) {
        float2 xv = __half22float2(xp[k2]);
        const float* wp0 = &sW[(k2 * 2 + 0) * NC];
        const float* wp1 = &sW[(k2 * 2 + 1) * NC];
#pragma unroll
        for (int c = 0; c < 16; c++) acc[c] += xv.x * wp0[c] + xv.y * wp1[c];
    }

    float dv = g_dinv[r];
    __half2* op = (__half2*)&g_h2[(size_t)r * NC];
#pragma unroll
    for (int q = 0; q < 8; q++)
        op[q] = __floats2half2_rn(acc[2 * q] * dv, acc[2 * q + 1] * dv);
}

// ---------------------------------------------------------------------------
// Gather 2 + log_softmax fused: 2 nodes per warp (16 lanes each), fp16 h2
// ---------------------------------------------------------------------------
__global__ __launch_bounds__(256) void gather2_softmax_kernel(float* __restrict__ out) {
    int w = (blockIdx.x * blockDim.x + threadIdx.x) >> 5;
    int lane = threadIdx.x & 31;
    int node = w * 2 + (lane >> 4);
    int l = lane & 15;
    if (node >= NN) return;

    int start = g_rowptr[node];
    int deg = g_cnt[node];
    float acc = 0.0f;
    int i = 0;
    for (; i + 4 <= deg; i += 4) {
        int s0 = g_srcv[start + i + 0];
        int s1 = g_srcv[start + i + 1];
        int s2 = g_srcv[start + i + 2];
        int s3 = g_srcv[start + i + 3];
        acc += __half2float(g_h2[(size_t)s0 * NC + l]) + __half2float(g_h2[(size_t)s1 * NC + l])
             + __half2float(g_h2[(size_t)s2 * NC + l]) + __half2float(g_h2[(size_t)s3 * NC + l]);
    }
    for (; i < deg; i++) acc += __half2float(g_h2[(size_t)g_srcv[start + i] * NC + l]);
    acc *= g_dinv[node];

    float m = acc;
#pragma unroll
    for (int off = 8; off > 0; off >>= 1)
        m = fmaxf(m, __shfl_xor_sync(0xffffffffu, m, off, 16));
    float ex = expf(acc - m);
    float s = ex;
#pragma unroll
    for (int off = 8; off > 0; off >>= 1)
        s += __shfl_xor_sync(0xffffffffu, s, off, 16);
    out[(size_t)node * NC + l] = (acc - m) - logf(s);
}

// ---------------------------------------------------------------------------
extern "C" void kernel_launch(void* const* d_in, const int* in_sizes, int n_in,
                              void* d_out, int out_size) {
    const float* x = (const float*)d_in[0];
    const int* ei = (const int*)d_in[1];
    const float* W1 = (const float*)d_in[2];
    const float* W2 = (const float*)d_in[3];
    float* out = (float*)d_out;

    zero_kernel<<<NBLK, 256>>>();
    fatA_kernel<<<G1A + EDGE_BLKS, 256>>>(x, W1, ei);   // mma gemm1 A ∥ deg
    scan_fused_kernel<<<NBLK, 256>>>();
    fatB_kernel<<<G1B + EDGE_BLKS, 256>>>(x, W1, ei);   // mma gemm1 B ∥ fill
    gather1_kernel<<<(NN * 32 + 255) / 256, 256>>>();
    gemm2_kernel<<<NBLK, 256>>>(W2);
    gather2_softmax_kernel<<<((NN + 1) / 2 * 32 + 255) / 256, 256>>>(out);
}